// round 15
// baseline (speedup 1.0000x reference)
#include <cuda_runtime.h>
#include <cstdint>

#define Bn 4
#define Tn 2048
#define Cn 768
#define Hn 12
#define Dn 64
#define Mrows (Bn * Tn)   // 8192
#define N_QKV (3 * Cn)    // 2304
#define NQB (Tn / 128)    // 16 q-blocks per (b,h)
#define NBH (Bn * Hn)     // 48

// ---- scratch (no allocs allowed) ----
__device__ float g_q[Bn * Hn * Tn * Dn];
__device__ float g_k[Bn * Hn * Tn * Dn];
__device__ float g_v[Bn * Hn * Tn * Dn];
__device__ float g_att[Bn * Tn * Cn];

#define SMP 132   // smem row stride: multiple of 4 floats -> 16B-aligned rows for LDS.128

// ---- packed fp32x2 helpers (sm_103a FFMA2 path; bit-exact per lane) ----
typedef unsigned long long u64t;
__device__ __forceinline__ u64t fma2(u64t a, u64t b, u64t c) {
    u64t r; asm("fma.rn.f32x2 %0, %1, %2, %3;" : "=l"(r) : "l"(a), "l"(b), "l"(c)); return r;
}
__device__ __forceinline__ u64t mul2(u64t a, u64t b) {
    u64t r; asm("mul.rn.f32x2 %0, %1, %2;" : "=l"(r) : "l"(a), "l"(b)); return r;
}
__device__ __forceinline__ u64t pack2(float lo, float hi) {
    u64t r; asm("mov.b64 %0, {%1, %2};" : "=l"(r) : "f"(lo), "f"(hi)); return r;
}
__device__ __forceinline__ float2 unpack2(u64t v) {
    float lo, hi; asm("mov.b64 {%0, %1}, %2;" : "=f"(lo), "=f"(hi) : "l"(v));
    return make_float2(lo, hi);
}

// ---- cp.async helpers (16B, L1-bypass) ----
__device__ __forceinline__ void cpa16(uint32_t saddr, const void* gaddr) {
    asm volatile("cp.async.cg.shared.global [%0], [%1], 16;" :: "r"(saddr), "l"(gaddr));
}
__device__ __forceinline__ void cpa_commit() {
    asm volatile("cp.async.commit_group;");
}
__device__ __forceinline__ void cpa_wait1() {
    asm volatile("cp.async.wait_group 1;");
}
__device__ __forceinline__ void cpa_wait0() {
    asm volatile("cp.async.wait_group 0;");
}

// ============================================================================
// Kernel 1: qkv = x @ w_qkv^T, fused RoPE, scatter to [b,h,t,d]
// 128x128x16 tile, 256 threads, packed-f32x2 8x8 micro-tile.
// Register PREFETCH of next k-tile: LDG issued before compute, hiding latency.
// ============================================================================
__global__ __launch_bounds__(256) void qkv_rope_kernel(
    const float* __restrict__ x, const float* __restrict__ w,
    const float* __restrict__ rsin, const float* __restrict__ rcos)
{
    __shared__ float As[16][SMP];
    __shared__ float Bs[16][SMP];

    const int tid = threadIdx.x;
    const int tx = tid & 15;
    const int ty = tid >> 4;
    const int m0 = blockIdx.y * 128;
    const int n0 = blockIdx.x * 128;

    // per-thread tile-load slots: 2 float4 of A, 2 of B
    const int r0l = tid >> 2;            // u=0 row
    const int c0l = (tid & 3) * 4;       // col group
    const int r1l = (tid + 256) >> 2;    // u=1 row
    // (c1l == c0l since (tid+256)&3 == tid&3)

    u64t accp[8][4];
    #pragma unroll
    for (int i = 0; i < 8; i++)
        #pragma unroll
        for (int j = 0; j < 4; j++) accp[i][j] = 0ull;

    float4 apre[2], bpre[2];
    apre[0] = *(const float4*)&x[(m0 + r0l) * Cn + c0l];
    apre[1] = *(const float4*)&x[(m0 + r1l) * Cn + c0l];
    bpre[0] = *(const float4*)&w[(n0 + r0l) * Cn + c0l];
    bpre[1] = *(const float4*)&w[(n0 + r1l) * Cn + c0l];

    for (int k0 = 0; k0 < Cn; k0 += 16) {
        __syncthreads();   // prior compute done before overwriting smem
        {
            float4 a0 = apre[0], a1 = apre[1], b0 = bpre[0], b1 = bpre[1];
            As[c0l + 0][r0l] = a0.x; As[c0l + 1][r0l] = a0.y;
            As[c0l + 2][r0l] = a0.z; As[c0l + 3][r0l] = a0.w;
            As[c0l + 0][r1l] = a1.x; As[c0l + 1][r1l] = a1.y;
            As[c0l + 2][r1l] = a1.z; As[c0l + 3][r1l] = a1.w;
            Bs[c0l + 0][r0l] = b0.x; Bs[c0l + 1][r0l] = b0.y;
            Bs[c0l + 2][r0l] = b0.z; Bs[c0l + 3][r0l] = b0.w;
            Bs[c0l + 0][r1l] = b1.x; Bs[c0l + 1][r1l] = b1.y;
            Bs[c0l + 2][r1l] = b1.z; Bs[c0l + 3][r1l] = b1.w;
        }
        __syncthreads();

        // prefetch next k-tile while computing this one
        if (k0 + 16 < Cn) {
            const int kn = k0 + 16;
            apre[0] = *(const float4*)&x[(m0 + r0l) * Cn + kn + c0l];
            apre[1] = *(const float4*)&x[(m0 + r1l) * Cn + kn + c0l];
            bpre[0] = *(const float4*)&w[(n0 + r0l) * Cn + kn + c0l];
            bpre[1] = *(const float4*)&w[(n0 + r1l) * Cn + kn + c0l];
        }

        #pragma unroll
        for (int kk = 0; kk < 16; kk++) {
            float4 a0 = *(const float4*)&As[kk][ty * 8];
            float4 a1 = *(const float4*)&As[kk][ty * 8 + 4];
            ulonglong2 b01 = *(const ulonglong2*)&Bs[kk][tx * 8];
            ulonglong2 b23 = *(const ulonglong2*)&Bs[kk][tx * 8 + 4];
            const u64t bp0 = b01.x, bp1 = b01.y, bp2 = b23.x, bp3 = b23.y;
            float ar[8] = {a0.x, a0.y, a0.z, a0.w, a1.x, a1.y, a1.z, a1.w};
            #pragma unroll
            for (int i = 0; i < 8; i++) {
                const u64t ai = pack2(ar[i], ar[i]);
                accp[i][0] = fma2(ai, bp0, accp[i][0]);
                accp[i][1] = fma2(ai, bp1, accp[i][1]);
                accp[i][2] = fma2(ai, bp2, accp[i][2]);
                accp[i][3] = fma2(ai, bp3, accp[i][3]);
            }
        }
    }

    const int nbase = n0 + tx * 8;
    const int s   = nbase / Cn;
    const int rem = nbase % Cn;
    const int h   = rem / Dn;
    const int d0  = rem % Dn;

    #pragma unroll
    for (int i = 0; i < 8; i++) {
        const int m = m0 + ty * 8 + i;
        const int bb = m / Tn, t = m % Tn;
        float2 p0 = unpack2(accp[i][0]), p1 = unpack2(accp[i][1]);
        float2 p2 = unpack2(accp[i][2]), p3 = unpack2(accp[i][3]);
        float acc8[8] = {p0.x, p0.y, p1.x, p1.y, p2.x, p2.y, p3.x, p3.y};
        float* __restrict__ dst;
        float o[8];
        if (s == 2) {
            dst = g_v;
            #pragma unroll
            for (int j = 0; j < 8; j++) o[j] = acc8[j];
        } else {
            dst = (s == 0) ? g_q : g_k;
            const int i0 = d0 >> 1;
            #pragma unroll
            for (int p = 0; p < 4; p++) {
                float sp = rsin[t * (Dn / 2) + i0 + p];
                float cp = rcos[t * (Dn / 2) + i0 + p];
                float e = acc8[2 * p], f = acc8[2 * p + 1];
                o[2 * p]     = e * cp - f * sp;
                o[2 * p + 1] = e * sp + f * cp;
            }
        }
        const int base = ((bb * Hn + h) * Tn + t) * Dn + d0;
        float4 w0, w1;
        w0.x = o[0]; w0.y = o[1]; w0.z = o[2]; w0.w = o[3];
        w1.x = o[4]; w1.y = o[5]; w1.z = o[6]; w1.w = o[7];
        *(float4*)&dst[base]     = w0;
        *(float4*)&dst[base + 4] = w1;
    }
}

// ============================================================================
// Kernel 2: causal flash attention, packed f32x2 (FFMA2), cp.async double
// buffer, LPT-ordered 1-D grid. UNCHANGED from the 1638us passing version.
// ============================================================================
__global__ __launch_bounds__(128) void attn_kernel()
{
    __shared__ float Ks[2][32 * 64];
    __shared__ float Vs[2][32 * 64];

    const int tid = threadIdx.x;
    const int bid = blockIdx.x;
    const int qb = (NQB - 1) - (bid / NBH);
    const int bh = bid % NBH;
    const int q0 = qb * 128;

    const float* __restrict__ qptr = g_q + (size_t)bh * Tn * Dn;
    const float* __restrict__ kptr = g_k + (size_t)bh * Tn * Dn;
    const float* __restrict__ vptr = g_v + (size_t)bh * Tn * Dn;

    const uint32_t ks_s = (uint32_t)__cvta_generic_to_shared(&Ks[0][0]);
    const uint32_t vs_s = (uint32_t)__cvta_generic_to_shared(&Vs[0][0]);

    u64t qp[32];
    {
        const u64t sc2 = pack2(0.125f, 0.125f);
        const ulonglong2* qrow = (const ulonglong2*)&qptr[(size_t)(q0 + tid) * Dn];
        #pragma unroll
        for (int i = 0; i < 16; i++) {
            ulonglong2 qq = qrow[i];
            qp[2 * i + 0] = mul2(qq.x, sc2);
            qp[2 * i + 1] = mul2(qq.y, sc2);
        }
    }

    const int t_q = q0 + tid;
    float m_run = -1e30f, l_run = 0.f;
    u64t accp[32];
    #pragma unroll
    for (int i = 0; i < 32; i++) accp[i] = 0ull;

    const int ntiles = (q0 + 128) / 32;

    auto issue_tile = [&](int kt) {
        const int base_r = kt * 32;
        const uint32_t soff = (uint32_t)((kt & 1) * 32 * 64 * 4);
        #pragma unroll
        for (int u = 0; u < 4; u++) {
            const int idx = tid + u * 128;
            const int r = idx >> 4, c = (idx & 15) * 4;
            const uint32_t so = soff + (uint32_t)(r * 64 + c) * 4;
            cpa16(ks_s + so, &kptr[(base_r + r) * Dn + c]);
            cpa16(vs_s + so, &vptr[(base_r + r) * Dn + c]);
        }
        cpa_commit();
    };

    issue_tile(0);

    for (int kt = 0; kt < ntiles; kt++) {
        if (kt + 1 < ntiles) { issue_tile(kt + 1); cpa_wait1(); }
        else                 { cpa_wait0(); }
        __syncthreads();

        const float* __restrict__ Kb = &Ks[kt & 1][0];
        const float* __restrict__ Vb = &Vs[kt & 1][0];
        const int kbase = kt * 32;

        float sreg[32];
        float tmax = -1e30f;
        #pragma unroll
        for (int j = 0; j < 32; j += 4) {
            u64t a0 = 0ull, a1 = 0ull, a2 = 0ull, a3 = 0ull;
            #pragma unroll
            for (int d = 0; d < 64; d += 4) {
                const int pi = d >> 1;
                ulonglong2 k0 = *(const ulonglong2*)&Kb[(j + 0) * 64 + d];
                ulonglong2 k1 = *(const ulonglong2*)&Kb[(j + 1) * 64 + d];
                ulonglong2 k2 = *(const ulonglong2*)&Kb[(j + 2) * 64 + d];
                ulonglong2 k3 = *(const ulonglong2*)&Kb[(j + 3) * 64 + d];
                a0 = fma2(qp[pi], k0.x, a0); a0 = fma2(qp[pi + 1], k0.y, a0);
                a1 = fma2(qp[pi], k1.x, a1); a1 = fma2(qp[pi + 1], k1.y, a1);
                a2 = fma2(qp[pi], k2.x, a2); a2 = fma2(qp[pi + 1], k2.y, a2);
                a3 = fma2(qp[pi], k3.x, a3); a3 = fma2(qp[pi + 1], k3.y, a3);
            }
            float2 f0 = unpack2(a0), f1 = unpack2(a1), f2 = unpack2(a2), f3 = unpack2(a3);
            float s0 = f0.x + f0.y, s1 = f1.x + f1.y, s2 = f2.x + f2.y, s3 = f3.x + f3.y;
            if (kbase + j + 0 > t_q) s0 = -1e30f;
            if (kbase + j + 1 > t_q) s1 = -1e30f;
            if (kbase + j + 2 > t_q) s2 = -1e30f;
            if (kbase + j + 3 > t_q) s3 = -1e30f;
            sreg[j + 0] = s0; sreg[j + 1] = s1;
            sreg[j + 2] = s2; sreg[j + 3] = s3;
            tmax = fmaxf(tmax, fmaxf(fmaxf(s0, s1), fmaxf(s2, s3)));
        }

        const float m_new = fmaxf(m_run, tmax);
        const float corr = __expf(m_run - m_new);
        const u64t corr2 = pack2(corr, corr);
        l_run *= corr;
        #pragma unroll
        for (int i = 0; i < 32; i++) accp[i] = mul2(accp[i], corr2);
        m_run = m_new;

        float lsum = 0.f;
        #pragma unroll
        for (int j = 0; j < 32; j += 4) {
            float p0 = __expf(sreg[j + 0] - m_new);
            float p1 = __expf(sreg[j + 1] - m_new);
            float p2 = __expf(sreg[j + 2] - m_new);
            float p3 = __expf(sreg[j + 3] - m_new);
            lsum += (p0 + p1) + (p2 + p3);
            const u64t pj0 = pack2(p0, p0), pj1 = pack2(p1, p1);
            const u64t pj2 = pack2(p2, p2), pj3 = pack2(p3, p3);
            #pragma unroll
            for (int d = 0; d < 64; d += 4) {
                const int pi = d >> 1;
                ulonglong2 v0 = *(const ulonglong2*)&Vb[(j + 0) * 64 + d];
                ulonglong2 v1 = *(const ulonglong2*)&Vb[(j + 1) * 64 + d];
                ulonglong2 v2 = *(const ulonglong2*)&Vb[(j + 2) * 64 + d];
                ulonglong2 v3 = *(const ulonglong2*)&Vb[(j + 3) * 64 + d];
                accp[pi]     = fma2(pj3, v3.x, fma2(pj2, v2.x, fma2(pj1, v1.x, fma2(pj0, v0.x, accp[pi]))));
                accp[pi + 1] = fma2(pj3, v3.y, fma2(pj2, v2.y, fma2(pj1, v1.y, fma2(pj0, v0.y, accp[pi + 1]))));
            }
        }
        l_run += lsum;

        __syncthreads();
    }

    const float inv = 1.f / l_run;
    const u64t inv2 = pack2(inv, inv);
    const int bb = bh / Hn, h = bh % Hn;
    float* outp = g_att + ((size_t)(bb * Tn + t_q)) * Cn + h * Dn;
    #pragma unroll
    for (int i = 0; i < 32; i += 2) {
        ulonglong2 o;
        o.x = mul2(accp[i],     inv2);
        o.y = mul2(accp[i + 1], inv2);
        *(ulonglong2*)&outp[i * 2] = o;
    }
}

// ============================================================================
// Kernel 3: out = g_att @ w_proj^T — packed 8x8 scheme + register prefetch
// ============================================================================
__global__ __launch_bounds__(256) void proj_kernel(
    const float* __restrict__ wp, float* __restrict__ out)
{
    __shared__ float As[16][SMP];
    __shared__ float Bs[16][SMP];

    const int tid = threadIdx.x;
    const int tx = tid & 15;
    const int ty = tid >> 4;
    const int m0 = blockIdx.y * 128;
    const int n0 = blockIdx.x * 128;

    const int r0l = tid >> 2;
    const int c0l = (tid & 3) * 4;
    const int r1l = (tid + 256) >> 2;

    u64t accp[8][4];
    #pragma unroll
    for (int i = 0; i < 8; i++)
        #pragma unroll
        for (int j = 0; j < 4; j++) accp[i][j] = 0ull;

    float4 apre[2], bpre[2];
    apre[0] = *(const float4*)&g_att[(m0 + r0l) * Cn + c0l];
    apre[1] = *(const float4*)&g_att[(m0 + r1l) * Cn + c0l];
    bpre[0] = *(const float4*)&wp[(n0 + r0l) * Cn + c0l];
    bpre[1] = *(const float4*)&wp[(n0 + r1l) * Cn + c0l];

    for (int k0 = 0; k0 < Cn; k0 += 16) {
        __syncthreads();
        {
            float4 a0 = apre[0], a1 = apre[1], b0 = bpre[0], b1 = bpre[1];
            As[c0l + 0][r0l] = a0.x; As[c0l + 1][r0l] = a0.y;
            As[c0l + 2][r0l] = a0.z; As[c0l + 3][r0l] = a0.w;
            As[c0l + 0][r1l] = a1.x; As[c0l + 1][r1l] = a1.y;
            As[c0l + 2][r1l] = a1.z; As[c0l + 3][r1l] = a1.w;
            Bs[c0l + 0][r0l] = b0.x; Bs[c0l + 1][r0l] = b0.y;
            Bs[c0l + 2][r0l] = b0.z; Bs[c0l + 3][r0l] = b0.w;
            Bs[c0l + 0][r1l] = b1.x; Bs[c0l + 1][r1l] = b1.y;
            Bs[c0l + 2][r1l] = b1.z; Bs[c0l + 3][r1l] = b1.w;
        }
        __syncthreads();

        if (k0 + 16 < Cn) {
            const int kn = k0 + 16;
            apre[0] = *(const float4*)&g_att[(m0 + r0l) * Cn + kn + c0l];
            apre[1] = *(const float4*)&g_att[(m0 + r1l) * Cn + kn + c0l];
            bpre[0] = *(const float4*)&wp[(n0 + r0l) * Cn + kn + c0l];
            bpre[1] = *(const float4*)&wp[(n0 + r1l) * Cn + kn + c0l];
        }

        #pragma unroll
        for (int kk = 0; kk < 16; kk++) {
            float4 a0 = *(const float4*)&As[kk][ty * 8];
            float4 a1 = *(const float4*)&As[kk][ty * 8 + 4];
            ulonglong2 b01 = *(const ulonglong2*)&Bs[kk][tx * 8];
            ulonglong2 b23 = *(const ulonglong2*)&Bs[kk][tx * 8 + 4];
            const u64t bp0 = b01.x, bp1 = b01.y, bp2 = b23.x, bp3 = b23.y;
            float ar[8] = {a0.x, a0.y, a0.z, a0.w, a1.x, a1.y, a1.z, a1.w};
            #pragma unroll
            for (int i = 0; i < 8; i++) {
                const u64t ai = pack2(ar[i], ar[i]);
                accp[i][0] = fma2(ai, bp0, accp[i][0]);
                accp[i][1] = fma2(ai, bp1, accp[i][1]);
                accp[i][2] = fma2(ai, bp2, accp[i][2]);
                accp[i][3] = fma2(ai, bp3, accp[i][3]);
            }
        }
    }

    #pragma unroll
    for (int i = 0; i < 8; i++) {
        const int m = m0 + ty * 8 + i;
        const int n = n0 + tx * 8;
        ulonglong2 w0, w1;
        w0.x = accp[i][0]; w0.y = accp[i][1];
        w1.x = accp[i][2]; w1.y = accp[i][3];
        *(ulonglong2*)&out[m * Cn + n]     = w0;
        *(ulonglong2*)&out[m * Cn + n + 4] = w1;
    }
}

// ============================================================================
extern "C" void kernel_launch(void* const* d_in, const int* in_sizes, int n_in,
                              void* d_out, int out_size)
{
    const float* x      = (const float*)d_in[0];
    const float* w_qkv  = (const float*)d_in[1];
    const float* w_proj = (const float*)d_in[2];
    const float* r_sin  = (const float*)d_in[3];
    const float* r_cos  = (const float*)d_in[4];
    float* out = (float*)d_out;

    // kernel 1: qkv + rope (packed f32x2 + register prefetch)
    {
        dim3 grid(N_QKV / 128, Mrows / 128);
        qkv_rope_kernel<<<grid, 256>>>(x, w_qkv, r_sin, r_cos);
    }

    // kernel 2: attention (packed f32x2, LPT-ordered 1-D grid)
    {
        attn_kernel<<<NQB * NBH, 128>>>();
    }

    // kernel 3: output projection (packed f32x2 + register prefetch)
    {
        dim3 grid(Cn / 128, Mrows / 128);
        proj_kernel<<<grid, 256>>>(w_proj, out);
    }
}